// round 5
// baseline (speedup 1.0000x reference)
#include <cuda_runtime.h>
#include <cstdint>

#define B_ 8
#define N_ 16384
#define M_ 1024
#define C_ 64
#define NS_ 32
#define COUT_ 67
#define R2_ 0.04f
#define TILE_PTS 1024

// Scratch: transposed features (B, N, C) = 32 MB, and ball-query indices = 1 MB.
__device__ float g_ft[(size_t)B_ * N_ * C_];
__device__ int   g_idx[(size_t)B_ * M_ * NS_];

// ---------------------------------------------------------------------------
// Kernel 1: transpose features (B, C, N) -> (B, N, C), float4 both directions.
// ---------------------------------------------------------------------------
__global__ void transpose_kernel(const float* __restrict__ f) {
    __shared__ float tile[32][33];       // tile[c][n]
    const int b  = blockIdx.z;
    const int n0 = blockIdx.x * 32;
    const int c0 = blockIdx.y * 32;
    const int tx = threadIdx.x;          // 0..7
    const int ty = threadIdx.y;          // 0..31

    const float* src = f + (size_t)b * C_ * N_;
    float*       dst = g_ft + (size_t)b * N_ * C_;

    const float4 v = *(const float4*)(src + (size_t)(c0 + ty) * N_ + n0 + tx * 4);
    tile[ty][tx * 4 + 0] = v.x;
    tile[ty][tx * 4 + 1] = v.y;
    tile[ty][tx * 4 + 2] = v.z;
    tile[ty][tx * 4 + 3] = v.w;
    __syncthreads();

    float4 o;
    o.x = tile[tx * 4 + 0][ty];
    o.y = tile[tx * 4 + 1][ty];
    o.z = tile[tx * 4 + 2][ty];
    o.w = tile[tx * 4 + 3][ty];
    *(float4*)(dst + (size_t)(n0 + ty) * C_ + c0 + tx * 4) = o;
}

// ---------------------------------------------------------------------------
// Kernel 2: ball query, register-resident cooperative scan.
// Block = 8 warps / 8 queries (same batch). Per 1024-pt tile:
//   - coalesced gmem->smem load, then each thread pulls its OWN 4 points
//     (warp w owns [w*128,(w+1)*128), lane slot s -> point w*128+s*32+lane)
//     into registers (4x LDS.128 total per thread per tile).
//   - Phase 1: every warp evaluates every unfinished query against its 128
//     register points as a 4-bit nibble; per-warp hit count via redux.
//   - Phase 2: prefix over warp counts; ballot-based ordered placement ONLY
//     for warps whose hits fall inside the first-32 window.
//   - Phase 3: totals/done flags; block-wide early exit.
// ---------------------------------------------------------------------------
__global__ void ballquery_kernel(const float* __restrict__ xyz,
                                 const float* __restrict__ new_xyz) {
    __shared__ float4 spts[TILE_PTS];    // 16 KB
    __shared__ int    scnt[8][8];        // [query][warp] hit counts this tile
    __shared__ int    sres[8][NS_];      // first-32 indices
    __shared__ int    stot[8];           // accumulated totals
    __shared__ int    sdone[8];
    __shared__ int    sdone_cnt;
    __shared__ float  sq[8][3];

    const int tid  = threadIdx.x;
    const int w    = tid >> 5;
    const int lane = tid & 31;
    const int qbase = blockIdx.x * 8;    // all 8 queries in same batch
    const int b     = qbase >> 10;
    const float* xb = xyz + (size_t)b * N_ * 3;

    if (tid < 8) {
        stot[tid]  = 0;
        sdone[tid] = 0;
        const float* qp = new_xyz + (size_t)(qbase + tid) * 3;
        sq[tid][0] = qp[0]; sq[tid][1] = qp[1]; sq[tid][2] = qp[2];
    }
    if (tid == 0) sdone_cnt = 0;
    __syncthreads();

    const unsigned ltm = (1u << lane) - 1u;

    for (int t0 = 0; t0 < N_; t0 += TILE_PTS) {
        // Coalesced tile load: 4 points per thread via 3 float4 gmem reads.
        {
            const float4* src = (const float4*)(xb + (size_t)t0 * 3);
            const float4 a = src[tid * 3 + 0];
            const float4 c = src[tid * 3 + 1];
            const float4 d = src[tid * 3 + 2];
            spts[tid * 4 + 0] = make_float4(a.x, a.y, a.z, 0.f);
            spts[tid * 4 + 1] = make_float4(a.w, c.x, c.y, 0.f);
            spts[tid * 4 + 2] = make_float4(c.z, c.w, d.x, 0.f);
            spts[tid * 4 + 3] = make_float4(d.y, d.z, d.w, 0.f);
        }
        __syncthreads();

        // Pull own 4 points into registers (once per tile).
        float px[4], py[4], pz[4];
#pragma unroll
        for (int s = 0; s < 4; s++) {
            const float4 p = spts[w * 128 + s * 32 + lane];
            px[s] = p.x; py[s] = p.y; pz[s] = p.z;
        }

        // Phase 1: nibble masks + per-warp counts for all unfinished queries.
        unsigned nib[8];
#pragma unroll
        for (int q = 0; q < 8; q++) {
            nib[q] = 0u;
            if (!sdone[q]) {
                const float qx = sq[q][0], qy = sq[q][1], qz = sq[q][2];
                unsigned m = 0u;
#pragma unroll
                for (int s = 0; s < 4; s++) {
                    const float dx = px[s] - qx;
                    const float dy = py[s] - qy;
                    const float dz = pz[s] - qz;
                    if (dx * dx + dy * dy + dz * dz < R2_) m |= 1u << s;
                }
                nib[q] = m;
                const int wsum = __reduce_add_sync(0xffffffffu, __popc(m));
                if (lane == 0) scnt[q][w] = wsum;
            }
        }
        __syncthreads();

        // Phase 2: ordered placement (only when inside the first-32 window).
#pragma unroll 1
        for (int q = 0; q < 8; q++) {
            if (sdone[q]) continue;
            int pre = stot[q];
#pragma unroll
            for (int w2 = 0; w2 < 8; w2++)
                if (w2 < w) pre += scnt[q][w2];
            if (pre < NS_) {
                unsigned msk[4];
#pragma unroll
                for (int s = 0; s < 4; s++)
                    msk[s] = __ballot_sync(0xffffffffu, (nib[q] >> s) & 1u);
                int base_s = 0;
#pragma unroll
                for (int s = 0; s < 4; s++) {
                    if ((nib[q] >> s) & 1u) {
                        const int pos = pre + base_s + __popc(msk[s] & ltm);
                        if (pos < NS_)
                            sres[q][pos] = t0 + w * 128 + s * 32 + lane;
                    }
                    base_s += __popc(msk[s]);
                }
            }
        }
        __syncthreads();

        // Phase 3: update totals / done flags.
        if (tid < 8) {
            const int q = tid;
            if (!sdone[q]) {
                int sum = 0;
#pragma unroll
                for (int w2 = 0; w2 < 8; w2++) sum += scnt[q][w2];
                const int nt = stot[q] + sum;
                stot[q] = nt;
                if (nt >= NS_) { sdone[q] = 1; atomicAdd(&sdone_cnt, 1); }
            }
        }
        __syncthreads();
        if (sdone_cnt == 8) break;
    }

    // Epilogue: warp w writes query w. total==0 -> clamp to N-1.
    {
        const int cur = min(stot[w], NS_);
        int v;
        if (cur == 0) v = N_ - 1;
        else          v = (lane < cur) ? sres[w][lane] : sres[w][0];
        g_idx[(size_t)(qbase + w) * NS_ + lane] = v;
    }
}

// ---------------------------------------------------------------------------
// Kernel 3: grouping. One block per (b, m). Gather 64 contiguous channels per
// index from the transposed features (256B coalesced per sample), plus the
// xyz diff; stage in a 67x33 smem tile; write output fully coalesced.
// ---------------------------------------------------------------------------
__global__ void group_kernel(const float* __restrict__ xyz,
                             const float* __restrict__ new_xyz,
                             float* __restrict__ out) {
    __shared__ int   sidx[NS_];
    __shared__ float tile[COUT_][33];

    const int bm = blockIdx.x;
    const int b  = bm >> 10;
    const int m  = bm & (M_ - 1);
    const int t  = threadIdx.x;          // 256 threads
    const int w  = t >> 5;
    const int lane = t & 31;

    if (t < NS_) sidx[t] = g_idx[(size_t)bm * NS_ + t];
    __syncthreads();

    const float* ftb = g_ft + (size_t)b * N_ * C_;
    const float* qp  = new_xyz + ((size_t)b * M_ + m) * 3;

#pragma unroll
    for (int k = 0; k < 4; k++) {
        const int s = w + k * 8;         // 8 warps cover 32 samples
        const int n = sidx[s];
        const float* col = ftb + (size_t)n * C_;
        tile[3 + lane][s]      = col[lane];
        tile[3 + 32 + lane][s] = col[lane + 32];
        if (lane < 3)
            tile[lane][s] = xyz[((size_t)b * N_ + n) * 3 + lane] - qp[lane];
    }
    __syncthreads();

    float* ob = out + ((size_t)b * COUT_ * M_ + m) * NS_;
    for (int e = t; e < COUT_ * NS_; e += 256) {
        const int c = e >> 5;
        const int s = e & 31;
        ob[(size_t)c * M_ * NS_ + s] = tile[c][s];
    }
}

// ---------------------------------------------------------------------------
extern "C" void kernel_launch(void* const* d_in, const int* in_sizes, int n_in,
                              void* d_out, int out_size) {
    const float* xyz = nullptr;
    const float* new_xyz = nullptr;
    const float* feats = nullptr;
    for (int i = 0; i < n_in; i++) {
        if (in_sizes[i] == B_ * N_ * 3)      xyz     = (const float*)d_in[i];
        else if (in_sizes[i] == B_ * M_ * 3) new_xyz = (const float*)d_in[i];
        else if (in_sizes[i] == B_ * C_ * N_) feats  = (const float*)d_in[i];
    }
    float* out = (float*)d_out;

    ballquery_kernel<<<(B_ * M_) / 8, 256>>>(xyz, new_xyz);

    dim3 tgrid(N_ / 32, C_ / 32, B_);
    transpose_kernel<<<tgrid, dim3(8, 32)>>>(feats);

    group_kernel<<<B_ * M_, 256>>>(xyz, new_xyz, out);
}